// round 2
// baseline (speedup 1.0000x reference)
#include <cuda_runtime.h>
#include <math.h>

// Problem constants
#define B_  32
#define C_  273
#define CP_ 288    // padded channel dim (stride of scores buffer, /16 exact)
#define T_  3000
#define O_  270
#define D_  2048   // 2 * 32^2
#define NF  32

// Scratch (allocation-free rule: __device__ globals)
__device__ float g_emb[(size_t)B_ * C_ * D_];       // [B*C, 2048]
__device__ float g_scores[(size_t)B_ * O_ * CP_];   // [B, 270, 288] padded, softmaxed in place

// Packed dual-fp32 FMA (Blackwell f32x2 pipe; ptxas never auto-emits this)
__device__ __forceinline__ void ffma2(float2& d, float2 a, float2 b) {
    asm("fma.rn.f32x2 %0, %1, %2, %0;"
        : "+l"(*reinterpret_cast<unsigned long long*>(&d))
        : "l"(*reinterpret_cast<unsigned long long*>(&a)),
          "l"(*reinterpret_cast<unsigned long long*>(&b)));
}

// ---------------------------------------------------------------------------
// Kernel 1: fourier embedding (mod-1 range reduction keeps fast-math safe)
// ---------------------------------------------------------------------------
__global__ __launch_bounds__(256) void emb_kernel(const float* __restrict__ layout) {
    int bc = blockIdx.x;
    float px = (layout[bc * 2 + 0] + 0.1f) / 1.2f;
    float py = (layout[bc * 2 + 1] + 0.1f) / 1.2f;
    float* e = g_emb + (size_t)bc * D_;
    for (int idx = threadIdx.x; idx < 1024; idx += blockDim.x) {
        int i = idx >> 5, j = idx & 31;
        float t = px * (float)i + py * (float)j;
        t -= floorf(t);
        float s, c;
        sincosf(6.28318530717958647692f * t, &s, &c);
        e[idx]        = s;
        e[idx + 1024] = c;
    }
}

// ---------------------------------------------------------------------------
// Kernel 2: scores[b,o,c] = sum_d heads[o,d] * emb[b,c,d]
// NT GEMM: M=270(o), N=273(c), K=2048. Tile 128x128x16, 128 thr, 8x16 microtile,
// f32x2 packed FMAs, register prefetch of next k-slab.
// ---------------------------------------------------------------------------
__global__ __launch_bounds__(128) void scores_kernel(const float* __restrict__ heads) {
    __shared__ float As[16][128];
    __shared__ float Bs[16][128];
    int b  = blockIdx.z;
    int m0 = blockIdx.y * 128;   // o
    int n0 = blockIdx.x * 128;   // c
    const float* Bm = g_emb + (size_t)b * C_ * D_;
    int t  = threadIdx.x;
    int tm = t >> 3;             // 0..15
    int tn = t & 7;              // 0..7
    int am = m0 + t;             // A row this thread loads
    int bn = n0 + t;             // B row this thread loads
    const float4 z4 = make_float4(0.f, 0.f, 0.f, 0.f);

    float2 acc[8][8];
#pragma unroll
    for (int i = 0; i < 8; i++)
#pragma unroll
        for (int j = 0; j < 8; j++) acc[i][j] = make_float2(0.f, 0.f);

    float4 rA[4], rB[4];
    // prefetch k-block 0
#pragma unroll
    for (int q = 0; q < 4; q++) {
        rA[q] = (am < O_) ? *(const float4*)(heads + (size_t)am * D_ + 4 * q) : z4;
        rB[q] = (bn < C_) ? *(const float4*)(Bm    + (size_t)bn * D_ + 4 * q) : z4;
    }

    for (int kb = 0; kb < D_ / 16; kb++) {
        __syncthreads();
#pragma unroll
        for (int q = 0; q < 4; q++) {
            As[4 * q + 0][t] = rA[q].x; As[4 * q + 1][t] = rA[q].y;
            As[4 * q + 2][t] = rA[q].z; As[4 * q + 3][t] = rA[q].w;
            Bs[4 * q + 0][t] = rB[q].x; Bs[4 * q + 1][t] = rB[q].y;
            Bs[4 * q + 2][t] = rB[q].z; Bs[4 * q + 3][t] = rB[q].w;
        }
        __syncthreads();
        if (kb + 1 < D_ / 16) {
            int k0 = (kb + 1) * 16;
#pragma unroll
            for (int q = 0; q < 4; q++) {
                rA[q] = (am < O_) ? *(const float4*)(heads + (size_t)am * D_ + k0 + 4 * q) : z4;
                rB[q] = (bn < C_) ? *(const float4*)(Bm    + (size_t)bn * D_ + k0 + 4 * q) : z4;
            }
        }
#pragma unroll
        for (int k = 0; k < 16; k++) {
            float4 a0 = *(const float4*)&As[k][tm * 8];
            float4 a1 = *(const float4*)&As[k][tm * 8 + 4];
            float2 bv[8];
#pragma unroll
            for (int q = 0; q < 4; q++) {
                float4 b4 = *(const float4*)&Bs[k][tn * 16 + 4 * q];
                bv[2 * q + 0] = make_float2(b4.x, b4.y);
                bv[2 * q + 1] = make_float2(b4.z, b4.w);
            }
            float a[8] = {a0.x, a0.y, a0.z, a0.w, a1.x, a1.y, a1.z, a1.w};
#pragma unroll
            for (int i = 0; i < 8; i++) {
                float2 aa = make_float2(a[i], a[i]);
#pragma unroll
                for (int j = 0; j < 8; j++) ffma2(acc[i][j], aa, bv[j]);
            }
        }
    }

    float* S = g_scores + (size_t)b * O_ * CP_;
#pragma unroll
    for (int i = 0; i < 8; i++) {
        int m = m0 + tm * 8 + i;
        if (m >= O_) continue;
#pragma unroll
        for (int j = 0; j < 8; j++) {
            int n = n0 + tn * 16 + 2 * j;
            if (n < CP_) *(float2*)(S + (size_t)m * CP_ + n) = acc[i][j];
        }
    }
}

// ---------------------------------------------------------------------------
// Kernel 3: softmax over channels (273 real, pads -> 0), stride 288, in place.
// ---------------------------------------------------------------------------
__global__ __launch_bounds__(256) void softmax_kernel() {
    int warp = (blockIdx.x * blockDim.x + threadIdx.x) >> 5;
    int lane = threadIdx.x & 31;
    if (warp >= B_ * O_) return;
    float* row = g_scores + (size_t)warp * CP_;

    float v[9];
    float m = -INFINITY;
#pragma unroll
    for (int i = 0; i < 9; i++) {
        int c = lane + i * 32;
        v[i] = (c < C_) ? row[c] : -INFINITY;
        m = fmaxf(m, v[i]);
    }
#pragma unroll
    for (int o = 16; o; o >>= 1) m = fmaxf(m, __shfl_xor_sync(0xffffffffu, m, o));
    float s = 0.f;
#pragma unroll
    for (int i = 0; i < 9; i++) {
        int c = lane + i * 32;
        if (c < C_) { v[i] = expf(v[i] - m); s += v[i]; }
    }
#pragma unroll
    for (int o = 16; o; o >>= 1) s += __shfl_xor_sync(0xffffffffu, s, o);
    float inv = 1.f / s;
#pragma unroll
    for (int i = 0; i < 9; i++) {
        int c = lane + i * 32;
        row[c] = (c < C_) ? v[i] * inv : 0.f;   // zero the pads (exact for out GEMM)
    }
}

// ---------------------------------------------------------------------------
// Kernel 4: out[b,o,t] = sum_c W[b,o,c] * brain[b,c,t]
// NN GEMM: M=270(o), N=3000(t), K=288 (padded, zero weights). Same tiling.
// ---------------------------------------------------------------------------
__global__ __launch_bounds__(128) void out_kernel(const float* __restrict__ brain,
                                                  float* __restrict__ out) {
    __shared__ float As[16][128];
    __shared__ float Bs[16][128];
    int b  = blockIdx.z;
    int m0 = blockIdx.y * 128;   // o
    int n0 = blockIdx.x * 128;   // t
    const float* Wb = g_scores + (size_t)b * O_ * CP_;
    const float* Xb = brain    + (size_t)b * C_ * T_;
    int t  = threadIdx.x;
    int tm = t >> 3;
    int tn = t & 7;
    int am  = m0 + t;            // A (weights) row this thread loads
    int bk  = t >> 3;            // B k-row within slab
    int bnc = n0 + (t & 7) * 16; // B col start
    const float4 z4 = make_float4(0.f, 0.f, 0.f, 0.f);

    float2 acc[8][8];
#pragma unroll
    for (int i = 0; i < 8; i++)
#pragma unroll
        for (int j = 0; j < 8; j++) acc[i][j] = make_float2(0.f, 0.f);

    float4 rA[4], rB[4];

    auto loadB = [&](int k0, float4* r) {
        int kk = k0 + bk;
        if (kk < C_) {
            const float* p = Xb + (size_t)kk * T_;
#pragma unroll
            for (int q = 0; q < 4; q++) {
                int n = bnc + 4 * q;
                if (n + 3 < T_) r[q] = *(const float4*)(p + n);
                else {
                    r[q] = z4;
                    if (n + 0 < T_) r[q].x = p[n + 0];
                    if (n + 1 < T_) r[q].y = p[n + 1];
                    if (n + 2 < T_) r[q].z = p[n + 2];
                }
            }
        } else {
#pragma unroll
            for (int q = 0; q < 4; q++) r[q] = z4;
        }
    };

    // prefetch k-block 0
#pragma unroll
    for (int q = 0; q < 4; q++)
        rA[q] = (am < O_) ? *(const float4*)(Wb + (size_t)am * CP_ + 4 * q) : z4;
    loadB(0, rB);

    const int KB = CP_ / 16;   // 18
    for (int kb = 0; kb < KB; kb++) {
        __syncthreads();
#pragma unroll
        for (int q = 0; q < 4; q++) {
            As[4 * q + 0][t] = rA[q].x; As[4 * q + 1][t] = rA[q].y;
            As[4 * q + 2][t] = rA[q].z; As[4 * q + 3][t] = rA[q].w;
        }
        *(float4*)&Bs[bk][(t & 7) * 16 + 0]  = rB[0];
        *(float4*)&Bs[bk][(t & 7) * 16 + 4]  = rB[1];
        *(float4*)&Bs[bk][(t & 7) * 16 + 8]  = rB[2];
        *(float4*)&Bs[bk][(t & 7) * 16 + 12] = rB[3];
        __syncthreads();
        if (kb + 1 < KB) {
            int k0 = (kb + 1) * 16;
#pragma unroll
            for (int q = 0; q < 4; q++)
                rA[q] = (am < O_) ? *(const float4*)(Wb + (size_t)am * CP_ + k0 + 4 * q) : z4;
            loadB(k0, rB);
        }
#pragma unroll
        for (int k = 0; k < 16; k++) {
            float4 a0 = *(const float4*)&As[k][tm * 8];
            float4 a1 = *(const float4*)&As[k][tm * 8 + 4];
            float2 bv[8];
#pragma unroll
            for (int q = 0; q < 4; q++) {
                float4 b4 = *(const float4*)&Bs[k][tn * 16 + 4 * q];
                bv[2 * q + 0] = make_float2(b4.x, b4.y);
                bv[2 * q + 1] = make_float2(b4.z, b4.w);
            }
            float a[8] = {a0.x, a0.y, a0.z, a0.w, a1.x, a1.y, a1.z, a1.w};
#pragma unroll
            for (int i = 0; i < 8; i++) {
                float2 aa = make_float2(a[i], a[i]);
#pragma unroll
                for (int j = 0; j < 8; j++) ffma2(acc[i][j], aa, bv[j]);
            }
        }
    }

    float* Ob = out + (size_t)b * O_ * T_;
#pragma unroll
    for (int i = 0; i < 8; i++) {
        int m = m0 + tm * 8 + i;
        if (m >= O_) continue;
#pragma unroll
        for (int j = 0; j < 8; j++) {
            int n = n0 + tn * 16 + 2 * j;
            if (n < T_) *(float2*)(Ob + (size_t)m * T_ + n) = acc[i][j];
        }
    }
}

// ---------------------------------------------------------------------------
extern "C" void kernel_launch(void* const* d_in, const int* in_sizes, int n_in,
                              void* d_out, int out_size) {
    const float* brain  = (const float*)d_in[0];  // [32, 273, 3000]
    const float* layout = (const float*)d_in[1];  // [32, 273, 2]
    const float* heads  = (const float*)d_in[2];  // [270, 2048]
    float* out = (float*)d_out;                   // [32, 270, 3000]

    emb_kernel<<<B_ * C_, 256>>>(layout);
    scores_kernel<<<dim3(3, 3, B_), 128>>>(heads);          // ceil(273/128), ceil(270/128)
    softmax_kernel<<<(B_ * O_ * 32 + 255) / 256, 256>>>();
    out_kernel<<<dim3((T_ + 127) / 128, 3, B_), 128>>>(brain, out);
}

// round 3
// speedup vs baseline: 5.2395x; 5.2395x over previous
#include <cuda_runtime.h>
#include <math.h>

// Problem constants
#define B_  32
#define C_  273
#define CP_ 288    // padded channel dim (stride of scores buffer)
#define T_  3000
#define O_  270
#define D_  2048   // 2 * 32^2

// Scratch (allocation-free rule: __device__ globals)
__device__ float g_emb[(size_t)B_ * C_ * D_];       // [B*C, 2048], tf32-rounded
__device__ float g_scores[(size_t)B_ * O_ * CP_];   // [B, 270, 288]; softmax writes tf32-rounded

// ---------------------------------------------------------------------------
// helpers
// ---------------------------------------------------------------------------
__device__ __forceinline__ unsigned tf32b(float x) {
    unsigned u; asm("cvt.rna.tf32.f32 %0, %1;" : "=r"(u) : "f"(x)); return u;
}
__device__ __forceinline__ float tf32f(float x) { return __uint_as_float(tf32b(x)); }

__device__ __forceinline__ void cp16(void* dst, const void* src, bool p) {
    unsigned d = (unsigned)__cvta_generic_to_shared(dst);
    int sz = p ? 16 : 0;
    asm volatile("cp.async.ca.shared.global [%0], [%1], 16, %2;" :: "r"(d), "l"(src), "r"(sz));
}
#define CP_COMMIT() asm volatile("cp.async.commit_group;")

__device__ __forceinline__ void mma8(float* c, const unsigned* a, const unsigned* b) {
    asm volatile("mma.sync.aligned.m16n8k8.row.col.f32.tf32.tf32.f32 "
        "{%0,%1,%2,%3},{%4,%5,%6,%7},{%8,%9},{%0,%1,%2,%3};"
        : "+f"(c[0]), "+f"(c[1]), "+f"(c[2]), "+f"(c[3])
        : "r"(a[0]), "r"(a[1]), "r"(a[2]), "r"(a[3]), "r"(b[0]), "r"(b[1]));
}

// ---------------------------------------------------------------------------
// Kernel 1: fourier embedding, output pre-rounded to tf32 (B operand of scores)
// ---------------------------------------------------------------------------
__global__ __launch_bounds__(256) void emb_kernel(const float* __restrict__ layout) {
    int bc = blockIdx.x;
    float px = (layout[bc * 2 + 0] + 0.1f) / 1.2f;
    float py = (layout[bc * 2 + 1] + 0.1f) / 1.2f;
    float* e = g_emb + (size_t)bc * D_;
    for (int idx = threadIdx.x; idx < 1024; idx += blockDim.x) {
        int i = idx >> 5, j = idx & 31;
        float t = px * (float)i + py * (float)j;
        t -= floorf(t);
        float s, c;
        sincosf(6.28318530717958647692f * t, &s, &c);
        e[idx]        = tf32f(s);
        e[idx + 1024] = tf32f(c);
    }
}

// ---------------------------------------------------------------------------
// Kernel 2: scores[b,o,c] = sum_d heads[o,d] * emb[b,c,d]   (both K-major)
// mma.sync tf32, CTA tile 64x64, 4 warps (2x2, each 32x32), K-chunk 32,
// cp.async double buffer.
// ---------------------------------------------------------------------------
__global__ __launch_bounds__(128) void scores_kernel(const float* __restrict__ heads) {
    __shared__ float As[2][64][36];   // [m][k], stride 36 -> conflict-free frags
    __shared__ float Bs[2][64][36];   // [n(c)][k]
    int b  = blockIdx.z;
    int m0 = blockIdx.y * 64;
    int n0 = blockIdx.x * 64;
    const float* E = g_emb + (size_t)b * C_ * D_;
    int t = threadIdx.x;
    int w = t >> 5, lane = t & 31;
    int wm = (w >> 1) * 32, wn = (w & 1) * 32;
    int g = lane >> 2, q4 = lane & 3;

    float acc[2][4][4] = {};

    auto load = [&](int kb, int s) {
        int k0 = kb * 32;
#pragma unroll
        for (int q = 0; q < 4; q++) {
            int idx = t + 128 * q;
            int r = idx >> 3, c4 = (idx & 7) * 4;
            bool pa = (m0 + r) < O_;
            cp16(&As[s][r][c4], heads + (size_t)(pa ? m0 + r : 0) * D_ + k0 + c4, pa);
            bool pb = (n0 + r) < C_;
            cp16(&Bs[s][r][c4], E + (size_t)(pb ? n0 + r : 0) * D_ + k0 + c4, pb);
        }
        CP_COMMIT();
    };

    load(0, 0);
    const int KB = D_ / 32;   // 64
    for (int kb = 0; kb < KB; kb++) {
        int s = kb & 1;
        if (kb + 1 < KB) {
            load(kb + 1, s ^ 1);
            asm volatile("cp.async.wait_group 1;");
        } else {
            asm volatile("cp.async.wait_group 0;");
        }
        __syncthreads();
#pragma unroll
        for (int k8 = 0; k8 < 4; k8++) {
            int kk = k8 * 8;
            unsigned a[2][4], bf[4][2];
#pragma unroll
            for (int i = 0; i < 2; i++) {
                a[i][0] = tf32b(As[s][wm + i * 16 + g    ][kk + q4    ]);
                a[i][1] = tf32b(As[s][wm + i * 16 + g + 8][kk + q4    ]);
                a[i][2] = tf32b(As[s][wm + i * 16 + g    ][kk + q4 + 4]);
                a[i][3] = tf32b(As[s][wm + i * 16 + g + 8][kk + q4 + 4]);
            }
#pragma unroll
            for (int j = 0; j < 4; j++) {   // emb pre-rounded: no cvt needed
                bf[j][0] = __float_as_uint(Bs[s][wn + j * 8 + g][kk + q4    ]);
                bf[j][1] = __float_as_uint(Bs[s][wn + j * 8 + g][kk + q4 + 4]);
            }
#pragma unroll
            for (int i = 0; i < 2; i++)
#pragma unroll
                for (int j = 0; j < 4; j++) mma8(acc[i][j], a[i], bf[j]);
        }
        __syncthreads();
    }

    float* S = g_scores + (size_t)b * O_ * CP_;
#pragma unroll
    for (int i = 0; i < 2; i++)
#pragma unroll
        for (int j = 0; j < 4; j++) {
            int m = m0 + wm + i * 16 + g;
            int n = n0 + wn + j * 8 + 2 * q4;
            if (n < CP_) {
                if (m < O_)
                    *(float2*)(S + (size_t)m * CP_ + n) = make_float2(acc[i][j][0], acc[i][j][1]);
                if (m + 8 < O_)
                    *(float2*)(S + (size_t)(m + 8) * CP_ + n) = make_float2(acc[i][j][2], acc[i][j][3]);
            }
        }
}

// ---------------------------------------------------------------------------
// Kernel 3: softmax over channels (273 real), stride 288, pads -> 0,
// output pre-rounded to tf32 (A operand of out GEMM).
// ---------------------------------------------------------------------------
__global__ __launch_bounds__(256) void softmax_kernel() {
    int warp = (blockIdx.x * blockDim.x + threadIdx.x) >> 5;
    int lane = threadIdx.x & 31;
    if (warp >= B_ * O_) return;
    float* row = g_scores + (size_t)warp * CP_;

    float v[9];
    float m = -INFINITY;
#pragma unroll
    for (int i = 0; i < 9; i++) {
        int c = lane + i * 32;
        v[i] = (c < C_) ? row[c] : -INFINITY;
        m = fmaxf(m, v[i]);
    }
#pragma unroll
    for (int o = 16; o; o >>= 1) m = fmaxf(m, __shfl_xor_sync(0xffffffffu, m, o));
    float s = 0.f;
#pragma unroll
    for (int i = 0; i < 9; i++) {
        int c = lane + i * 32;
        if (c < C_) { v[i] = expf(v[i] - m); s += v[i]; }
    }
#pragma unroll
    for (int o = 16; o; o >>= 1) s += __shfl_xor_sync(0xffffffffu, s, o);
    float inv = 1.f / s;
#pragma unroll
    for (int i = 0; i < 9; i++) {
        int c = lane + i * 32;
        row[c] = (c < C_) ? tf32f(v[i] * inv) : 0.f;
    }
}

// ---------------------------------------------------------------------------
// Kernel 4: out[b,o,t] = sum_c W[b,o,c] * brain[b,c,t]
// mma.sync tf32, CTA tile 64x128, 8 warps (2x4, each 32x32), K-chunk 16.
// ---------------------------------------------------------------------------
__global__ __launch_bounds__(256) void out_kernel(const float* __restrict__ brain,
                                                  float* __restrict__ out) {
    __shared__ float As[2][64][20];    // [m][k], stride 20 -> conflict-free
    __shared__ float Bs[2][16][136];   // [k][n], stride 136 -> conflict-free
    int b  = blockIdx.z;
    int m0 = blockIdx.y * 64;
    int n0 = blockIdx.x * 128;
    const float* W = g_scores + (size_t)b * O_ * CP_;
    const float* X = brain    + (size_t)b * C_ * T_;
    int t = threadIdx.x;
    int w = t >> 5, lane = t & 31;
    int wm = (w >> 2) * 32, wn = (w & 3) * 32;
    int g = lane >> 2, q4 = lane & 3;

    float acc[2][4][4] = {};

    auto load = [&](int kb, int s) {
        int k0 = kb * 16;
        {   // A: 64 x 16 floats = 256 float4, 1 per thread
            int r = t >> 2, c4 = (t & 3) * 4;
            bool pa = (m0 + r) < O_;
            cp16(&As[s][r][c4], W + (size_t)(pa ? m0 + r : 0) * CP_ + k0 + c4, pa);
        }
#pragma unroll
        for (int q = 0; q < 2; q++) {   // B: 16 x 128 floats = 512 float4, 2 per thread
            int idx = t + 256 * q;
            int r = idx >> 5, c4 = (idx & 31) * 4;
            int kk = k0 + r, n = n0 + c4;
            bool pb = (kk < C_) && (n < T_);
            cp16(&Bs[s][r][c4], X + (size_t)(pb ? kk : 0) * T_ + (pb ? n : 0), pb);
        }
        CP_COMMIT();
    };

    load(0, 0);
    const int KB = CP_ / 16;   // 18
    for (int kb = 0; kb < KB; kb++) {
        int s = kb & 1;
        if (kb + 1 < KB) {
            load(kb + 1, s ^ 1);
            asm volatile("cp.async.wait_group 1;");
        } else {
            asm volatile("cp.async.wait_group 0;");
        }
        __syncthreads();
#pragma unroll
        for (int k8 = 0; k8 < 2; k8++) {
            int kk = k8 * 8;
            unsigned a[2][4], bf[4][2];
#pragma unroll
            for (int i = 0; i < 2; i++) {   // weights pre-rounded by softmax: no cvt
                a[i][0] = __float_as_uint(As[s][wm + i * 16 + g    ][kk + q4    ]);
                a[i][1] = __float_as_uint(As[s][wm + i * 16 + g + 8][kk + q4    ]);
                a[i][2] = __float_as_uint(As[s][wm + i * 16 + g    ][kk + q4 + 4]);
                a[i][3] = __float_as_uint(As[s][wm + i * 16 + g + 8][kk + q4 + 4]);
            }
#pragma unroll
            for (int j = 0; j < 4; j++) {
                bf[j][0] = tf32b(Bs[s][kk + q4    ][wn + j * 8 + g]);
                bf[j][1] = tf32b(Bs[s][kk + q4 + 4][wn + j * 8 + g]);
            }
#pragma unroll
            for (int i = 0; i < 2; i++)
#pragma unroll
                for (int j = 0; j < 4; j++) mma8(acc[i][j], a[i], bf[j]);
        }
        __syncthreads();
    }

    float* Ob = out + (size_t)b * O_ * T_;
#pragma unroll
    for (int i = 0; i < 2; i++)
#pragma unroll
        for (int j = 0; j < 4; j++) {
            int m = m0 + wm + i * 16 + g;
            int n = n0 + wn + j * 8 + 2 * q4;
            if (n < T_) {
                if (m < O_)
                    *(float2*)(Ob + (size_t)m * T_ + n) = make_float2(acc[i][j][0], acc[i][j][1]);
                if (m + 8 < O_)
                    *(float2*)(Ob + (size_t)(m + 8) * T_ + n) = make_float2(acc[i][j][2], acc[i][j][3]);
            }
        }
}

// ---------------------------------------------------------------------------
extern "C" void kernel_launch(void* const* d_in, const int* in_sizes, int n_in,
                              void* d_out, int out_size) {
    const float* brain  = (const float*)d_in[0];  // [32, 273, 3000]
    const float* layout = (const float*)d_in[1];  // [32, 273, 2]
    const float* heads  = (const float*)d_in[2];  // [270, 2048]
    float* out = (float*)d_out;                   // [32, 270, 3000]

    emb_kernel<<<B_ * C_, 256>>>(layout);
    scores_kernel<<<dim3(5, 5, B_), 128>>>(heads);          // 64x64 tiles
    softmax_kernel<<<(B_ * O_ * 32 + 255) / 256, 256>>>();
    out_kernel<<<dim3(24, 5, B_), 256>>>(brain, out);       // 128n x 64m tiles
}

// round 4
// speedup vs baseline: 6.4073x; 1.2229x over previous
#include <cuda_runtime.h>
#include <math.h>

// Problem constants
#define B_  32
#define C_  273
#define CP_ 288    // padded channel dim (stride of scores buffer)
#define T_  3000
#define O_  270
#define D_  2048   // 2 * 32^2

// Scratch (allocation-free rule: __device__ globals)
__device__ float g_emb[(size_t)B_ * C_ * D_];       // [B*C, 2048], tf32-rounded
__device__ float g_scores[(size_t)B_ * O_ * CP_];   // [B, 270, 288]; softmax writes tf32-rounded
__device__ float g_headsr[(size_t)O_ * D_];         // heads, tf32-rounded

// ---------------------------------------------------------------------------
// helpers
// ---------------------------------------------------------------------------
__device__ __forceinline__ unsigned tf32b(float x) {
    unsigned u; asm("cvt.rna.tf32.f32 %0, %1;" : "=r"(u) : "f"(x)); return u;
}
__device__ __forceinline__ float tf32f(float x) { return __uint_as_float(tf32b(x)); }

__device__ __forceinline__ void cp16(void* dst, const void* src, bool p) {
    unsigned d = (unsigned)__cvta_generic_to_shared(dst);
    int sz = p ? 16 : 0;
    asm volatile("cp.async.ca.shared.global [%0], [%1], 16, %2;" :: "r"(d), "l"(src), "r"(sz));
}
#define CP_COMMIT() asm volatile("cp.async.commit_group;")

__device__ __forceinline__ void mma8(float* c, const unsigned* a, const unsigned* b) {
    asm volatile("mma.sync.aligned.m16n8k8.row.col.f32.tf32.tf32.f32 "
        "{%0,%1,%2,%3},{%4,%5,%6,%7},{%8,%9},{%0,%1,%2,%3};"
        : "+f"(c[0]), "+f"(c[1]), "+f"(c[2]), "+f"(c[3])
        : "r"(a[0]), "r"(a[1]), "r"(a[2]), "r"(a[3]), "r"(b[0]), "r"(b[1]));
}

// ---------------------------------------------------------------------------
// Kernel 0: round heads to tf32 once (removes cvt from scores inner loop)
// ---------------------------------------------------------------------------
__global__ __launch_bounds__(256) void round_heads_kernel(const float* __restrict__ heads) {
    int i = blockIdx.x * 256 + threadIdx.x;
    if (i < O_ * D_) g_headsr[i] = tf32f(heads[i]);
}

// ---------------------------------------------------------------------------
// Kernel 1: fourier embedding via angle addition: only 64 sincos per channel,
// then sin(a+b)/cos(a+b) outer-product combines. Output tf32-rounded.
// ---------------------------------------------------------------------------
__global__ __launch_bounds__(256) void emb_kernel(const float* __restrict__ layout) {
    __shared__ float sx[32], cx[32], sy[32], cy[32];
    int bc = blockIdx.x;
    float px = (layout[bc * 2 + 0] + 0.1f) / 1.2f;
    float py = (layout[bc * 2 + 1] + 0.1f) / 1.2f;
    if (threadIdx.x < 64) {
        int axis = threadIdx.x >> 5;
        int i = threadIdx.x & 31;
        float p = axis ? py : px;
        float t = p * (float)i;
        t -= floorf(t);
        float s, c;
        sincosf(6.28318530717958647692f * t, &s, &c);
        if (axis == 0) { sx[i] = s; cx[i] = c; }
        else           { sy[i] = s; cy[i] = c; }
    }
    __syncthreads();
    float* e = g_emb + (size_t)bc * D_;
    for (int idx = threadIdx.x; idx < 1024; idx += 256) {
        int i = idx >> 5, j = idx & 31;
        float si = sx[i], ci = cx[i], sj = sy[j], cj = cy[j];
        e[idx]        = tf32f(si * cj + ci * sj);   // sin(a+b)
        e[idx + 1024] = tf32f(ci * cj - si * sj);   // cos(a+b)
    }
}

// ---------------------------------------------------------------------------
// Kernel 2: scores[b,o,c] = sum_d headsr[o,d] * emb[b,c,d]   (both K-major)
// mma.sync tf32, CTA tile 96x96, 6 warps (3x2, each 32x48), K-chunk 32,
// cp.async double buffer. Operands pre-rounded -> no cvt in loop.
// ---------------------------------------------------------------------------
__global__ __launch_bounds__(192) void scores_kernel() {
    __shared__ float As[2][96][36];   // [m][k], stride 36 -> conflict-free frags
    __shared__ float Bs[2][96][36];   // [n(c)][k]
    int b  = blockIdx.z;
    int m0 = blockIdx.y * 96;
    int n0 = blockIdx.x * 96;
    const float* E = g_emb + (size_t)b * C_ * D_;
    int t = threadIdx.x;
    int w = t >> 5, lane = t & 31;
    int wm = (w >> 1) * 32, wn = (w & 1) * 48;
    int g = lane >> 2, q4 = lane & 3;

    float acc[2][6][4] = {};

    auto load = [&](int kb, int s) {
        int k0 = kb * 32;
#pragma unroll
        for (int q = 0; q < 4; q++) {
            int idx = t + 192 * q;
            int r = idx >> 3, c4 = (idx & 7) * 4;
            bool pa = (m0 + r) < O_;
            cp16(&As[s][r][c4], g_headsr + (size_t)(pa ? m0 + r : 0) * D_ + k0 + c4, pa);
            bool pb = (n0 + r) < C_;
            cp16(&Bs[s][r][c4], E + (size_t)(pb ? n0 + r : 0) * D_ + k0 + c4, pb);
        }
        CP_COMMIT();
    };

    load(0, 0);
    const int KB = D_ / 32;   // 64
    for (int kb = 0; kb < KB; kb++) {
        int s = kb & 1;
        if (kb + 1 < KB) {
            load(kb + 1, s ^ 1);
            asm volatile("cp.async.wait_group 1;");
        } else {
            asm volatile("cp.async.wait_group 0;");
        }
        __syncthreads();
#pragma unroll
        for (int k8 = 0; k8 < 4; k8++) {
            int kk = k8 * 8;
            unsigned a[2][4], bf[6][2];
#pragma unroll
            for (int i = 0; i < 2; i++) {
                a[i][0] = __float_as_uint(As[s][wm + i * 16 + g    ][kk + q4    ]);
                a[i][1] = __float_as_uint(As[s][wm + i * 16 + g + 8][kk + q4    ]);
                a[i][2] = __float_as_uint(As[s][wm + i * 16 + g    ][kk + q4 + 4]);
                a[i][3] = __float_as_uint(As[s][wm + i * 16 + g + 8][kk + q4 + 4]);
            }
#pragma unroll
            for (int j = 0; j < 6; j++) {
                bf[j][0] = __float_as_uint(Bs[s][wn + j * 8 + g][kk + q4    ]);
                bf[j][1] = __float_as_uint(Bs[s][wn + j * 8 + g][kk + q4 + 4]);
            }
#pragma unroll
            for (int i = 0; i < 2; i++)
#pragma unroll
                for (int j = 0; j < 6; j++) mma8(acc[i][j], a[i], bf[j]);
        }
        __syncthreads();
    }

    float* S = g_scores + (size_t)b * O_ * CP_;
#pragma unroll
    for (int i = 0; i < 2; i++)
#pragma unroll
        for (int j = 0; j < 6; j++) {
            int m = m0 + wm + i * 16 + g;
            int n = n0 + wn + j * 8 + 2 * q4;
            if (n < CP_) {
                if (m < O_)
                    *(float2*)(S + (size_t)m * CP_ + n) = make_float2(acc[i][j][0], acc[i][j][1]);
                if (m + 8 < O_)
                    *(float2*)(S + (size_t)(m + 8) * CP_ + n) = make_float2(acc[i][j][2], acc[i][j][3]);
            }
        }
}

// ---------------------------------------------------------------------------
// Kernel 3: softmax over channels (273 real), stride 288, pads -> 0,
// output pre-rounded to tf32 (A operand of out GEMM).
// ---------------------------------------------------------------------------
__global__ __launch_bounds__(256) void softmax_kernel() {
    int warp = (blockIdx.x * blockDim.x + threadIdx.x) >> 5;
    int lane = threadIdx.x & 31;
    if (warp >= B_ * O_) return;
    float* row = g_scores + (size_t)warp * CP_;

    float v[9];
    float m = -INFINITY;
#pragma unroll
    for (int i = 0; i < 9; i++) {
        int c = lane + i * 32;
        v[i] = (c < C_) ? row[c] : -INFINITY;
        m = fmaxf(m, v[i]);
    }
#pragma unroll
    for (int o = 16; o; o >>= 1) m = fmaxf(m, __shfl_xor_sync(0xffffffffu, m, o));
    float s = 0.f;
#pragma unroll
    for (int i = 0; i < 9; i++) {
        int c = lane + i * 32;
        if (c < C_) { v[i] = expf(v[i] - m); s += v[i]; }
    }
#pragma unroll
    for (int o = 16; o; o >>= 1) s += __shfl_xor_sync(0xffffffffu, s, o);
    float inv = 1.f / s;
#pragma unroll
    for (int i = 0; i < 9; i++) {
        int c = lane + i * 32;
        row[c] = (c < C_) ? tf32f(v[i] * inv) : 0.f;
    }
}

// ---------------------------------------------------------------------------
// Kernel 4: out[b,o,t] = sum_c W[b,o,c] * brain[b,c,t]
// mma.sync tf32, CTA tile 64x128, 8 warps (2x4, each 32x32), K-chunk 16.
// ---------------------------------------------------------------------------
__global__ __launch_bounds__(256) void out_kernel(const float* __restrict__ brain,
                                                  float* __restrict__ out) {
    __shared__ float As[2][64][20];    // [m][k], stride 20 -> conflict-free
    __shared__ float Bs[2][16][136];   // [k][n], stride 136 -> conflict-free
    int b  = blockIdx.z;
    int m0 = blockIdx.y * 64;
    int n0 = blockIdx.x * 128;
    const float* W = g_scores + (size_t)b * O_ * CP_;
    const float* X = brain    + (size_t)b * C_ * T_;
    int t = threadIdx.x;
    int w = t >> 5, lane = t & 31;
    int wm = (w >> 2) * 32, wn = (w & 3) * 32;
    int g = lane >> 2, q4 = lane & 3;

    float acc[2][4][4] = {};

    auto load = [&](int kb, int s) {
        int k0 = kb * 16;
        {   // A: 64 x 16 floats = 256 float4, 1 per thread
            int r = t >> 2, c4 = (t & 3) * 4;
            bool pa = (m0 + r) < O_;
            cp16(&As[s][r][c4], W + (size_t)(pa ? m0 + r : 0) * CP_ + k0 + c4, pa);
        }
#pragma unroll
        for (int q = 0; q < 2; q++) {   // B: 16 x 128 floats = 512 float4, 2 per thread
            int idx = t + 256 * q;
            int r = idx >> 5, c4 = (idx & 31) * 4;
            int kk = k0 + r, n = n0 + c4;
            bool pb = (kk < C_) && (n < T_);
            cp16(&Bs[s][r][c4], X + (size_t)(pb ? kk : 0) * T_ + (pb ? n : 0), pb);
        }
        CP_COMMIT();
    };

    load(0, 0);
    const int KB = CP_ / 16;   // 18
    for (int kb = 0; kb < KB; kb++) {
        int s = kb & 1;
        if (kb + 1 < KB) {
            load(kb + 1, s ^ 1);
            asm volatile("cp.async.wait_group 1;");
        } else {
            asm volatile("cp.async.wait_group 0;");
        }
        __syncthreads();
#pragma unroll
        for (int k8 = 0; k8 < 2; k8++) {
            int kk = k8 * 8;
            unsigned a[2][4], bf[4][2];
#pragma unroll
            for (int i = 0; i < 2; i++) {   // weights pre-rounded by softmax: no cvt
                a[i][0] = __float_as_uint(As[s][wm + i * 16 + g    ][kk + q4    ]);
                a[i][1] = __float_as_uint(As[s][wm + i * 16 + g + 8][kk + q4    ]);
                a[i][2] = __float_as_uint(As[s][wm + i * 16 + g    ][kk + q4 + 4]);
                a[i][3] = __float_as_uint(As[s][wm + i * 16 + g + 8][kk + q4 + 4]);
            }
#pragma unroll
            for (int j = 0; j < 4; j++) {
                bf[j][0] = tf32b(Bs[s][kk + q4    ][wn + j * 8 + g]);
                bf[j][1] = tf32b(Bs[s][kk + q4 + 4][wn + j * 8 + g]);
            }
#pragma unroll
            for (int i = 0; i < 2; i++)
#pragma unroll
                for (int j = 0; j < 4; j++) mma8(acc[i][j], a[i], bf[j]);
        }
        __syncthreads();
    }

    float* Ob = out + (size_t)b * O_ * T_;
#pragma unroll
    for (int i = 0; i < 2; i++)
#pragma unroll
        for (int j = 0; j < 4; j++) {
            int m = m0 + wm + i * 16 + g;
            int n = n0 + wn + j * 8 + 2 * q4;
            if (n < T_) {
                if (m < O_)
                    *(float2*)(Ob + (size_t)m * T_ + n) = make_float2(acc[i][j][0], acc[i][j][1]);
                if (m + 8 < O_)
                    *(float2*)(Ob + (size_t)(m + 8) * T_ + n) = make_float2(acc[i][j][2], acc[i][j][3]);
            }
        }
}

// ---------------------------------------------------------------------------
extern "C" void kernel_launch(void* const* d_in, const int* in_sizes, int n_in,
                              void* d_out, int out_size) {
    const float* brain  = (const float*)d_in[0];  // [32, 273, 3000]
    const float* layout = (const float*)d_in[1];  // [32, 273, 2]
    const float* heads  = (const float*)d_in[2];  // [270, 2048]
    float* out = (float*)d_out;                   // [32, 270, 3000]

    round_heads_kernel<<<(O_ * D_ + 255) / 256, 256>>>(heads);
    emb_kernel<<<B_ * C_, 256>>>(layout);
    scores_kernel<<<dim3(3, 3, B_), 192>>>();               // 96x96 tiles
    softmax_kernel<<<(B_ * O_ * 32 + 255) / 256, 256>>>();
    out_kernel<<<dim3(24, 5, B_), 256>>>(brain, out);       // 128n x 64m tiles
}

// round 5
// speedup vs baseline: 6.8726x; 1.0726x over previous
#include <cuda_runtime.h>
#include <math.h>

// Problem constants
#define B_  32
#define C_  273
#define CP_ 288    // padded channel dim (stride of scores buffer)
#define T_  3000
#define O_  270
#define D_  2048   // 2 * 32^2

// Scratch (allocation-free rule: __device__ globals)
__device__ float g_emb[(size_t)B_ * C_ * D_];       // [B*C, 2048], tf32-rounded
__device__ float g_scores[(size_t)B_ * O_ * CP_];   // [B, 270, 288]; softmax writes tf32-rounded
__device__ float g_headsr[(size_t)O_ * D_];         // heads, tf32-rounded

// ---------------------------------------------------------------------------
// helpers
// ---------------------------------------------------------------------------
__device__ __forceinline__ unsigned tf32b(float x) {
    unsigned u; asm("cvt.rna.tf32.f32 %0, %1;" : "=r"(u) : "f"(x)); return u;
}
__device__ __forceinline__ float tf32f(float x) { return __uint_as_float(tf32b(x)); }

__device__ __forceinline__ void cp16(void* dst, const void* src, bool p) {
    unsigned d = (unsigned)__cvta_generic_to_shared(dst);
    int sz = p ? 16 : 0;
    asm volatile("cp.async.ca.shared.global [%0], [%1], 16, %2;" :: "r"(d), "l"(src), "r"(sz));
}
#define CP_COMMIT() asm volatile("cp.async.commit_group;")
#define CP_WAIT0()  asm volatile("cp.async.wait_group 0;")

__device__ __forceinline__ void mma8(float* c, const unsigned* a, const unsigned* b) {
    asm volatile("mma.sync.aligned.m16n8k8.row.col.f32.tf32.tf32.f32 "
        "{%0,%1,%2,%3},{%4,%5,%6,%7},{%8,%9},{%0,%1,%2,%3};"
        : "+f"(c[0]), "+f"(c[1]), "+f"(c[2]), "+f"(c[3])
        : "r"(a[0]), "r"(a[1]), "r"(a[2]), "r"(a[3]), "r"(b[0]), "r"(b[1]));
}

// ---------------------------------------------------------------------------
// Kernel 0: round heads to tf32 once
// ---------------------------------------------------------------------------
__global__ __launch_bounds__(256) void round_heads_kernel(const float* __restrict__ heads) {
    int i = blockIdx.x * 256 + threadIdx.x;
    if (i < O_ * D_) g_headsr[i] = tf32f(heads[i]);
}

// ---------------------------------------------------------------------------
// Kernel 1: fourier embedding via angle addition (64 sincos + outer product)
// ---------------------------------------------------------------------------
__global__ __launch_bounds__(256) void emb_kernel(const float* __restrict__ layout) {
    __shared__ float sx[32], cx[32], sy[32], cy[32];
    int bc = blockIdx.x;
    float px = (layout[bc * 2 + 0] + 0.1f) / 1.2f;
    float py = (layout[bc * 2 + 1] + 0.1f) / 1.2f;
    if (threadIdx.x < 64) {
        int axis = threadIdx.x >> 5;
        int i = threadIdx.x & 31;
        float p = axis ? py : px;
        float t = p * (float)i;
        t -= floorf(t);
        float s, c;
        sincosf(6.28318530717958647692f * t, &s, &c);
        if (axis == 0) { sx[i] = s; cx[i] = c; }
        else           { sy[i] = s; cy[i] = c; }
    }
    __syncthreads();
    float* e = g_emb + (size_t)bc * D_;
    for (int idx = threadIdx.x; idx < 1024; idx += 256) {
        int i = idx >> 5, j = idx & 31;
        float si = sx[i], ci = cx[i], sj = sy[j], cj = cy[j];
        e[idx]        = tf32f(si * cj + ci * sj);   // sin(a+b)
        e[idx + 1024] = tf32f(ci * cj - si * sj);   // cos(a+b)
    }
}

// ---------------------------------------------------------------------------
// Kernel 2: scores[b,o,c] = sum_d headsr[o,d] * emb[b,c,d]
// mma.sync tf32, CTA 96x96, 6 warps (3x2, warp 32x48), K-chunk 32,
// double buffer, ONE syncthreads per k-block.
// ---------------------------------------------------------------------------
__global__ __launch_bounds__(192) void scores_kernel() {
    __shared__ float As[2][96][36];
    __shared__ float Bs[2][96][36];
    int b  = blockIdx.z;
    int m0 = blockIdx.y * 96;
    int n0 = blockIdx.x * 96;
    const float* E = g_emb + (size_t)b * C_ * D_;
    int t = threadIdx.x;
    int w = t >> 5, lane = t & 31;
    int wm = (w >> 1) * 32, wn = (w & 1) * 48;
    int g = lane >> 2, q4 = lane & 3;

    float acc[2][6][4] = {};

    auto load = [&](int kb, int s) {
        int k0 = kb * 32;
#pragma unroll
        for (int q = 0; q < 4; q++) {
            int idx = t + 192 * q;
            int r = idx >> 3, c4 = (idx & 7) * 4;
            bool pa = (m0 + r) < O_;
            cp16(&As[s][r][c4], g_headsr + (size_t)(pa ? m0 + r : 0) * D_ + k0 + c4, pa);
            bool pb = (n0 + r) < C_;
            cp16(&Bs[s][r][c4], E + (size_t)(pb ? n0 + r : 0) * D_ + k0 + c4, pb);
        }
        CP_COMMIT();
    };

    load(0, 0);
    const int KB = D_ / 32;   // 64
    for (int kb = 0; kb < KB; kb++) {
        int s = kb & 1;
        CP_WAIT0();
        __syncthreads();
        if (kb + 1 < KB) load(kb + 1, s ^ 1);
#pragma unroll
        for (int k8 = 0; k8 < 4; k8++) {
            int kk = k8 * 8;
            unsigned a[2][4], bf[6][2];
#pragma unroll
            for (int i = 0; i < 2; i++) {
                a[i][0] = __float_as_uint(As[s][wm + i * 16 + g    ][kk + q4    ]);
                a[i][1] = __float_as_uint(As[s][wm + i * 16 + g + 8][kk + q4    ]);
                a[i][2] = __float_as_uint(As[s][wm + i * 16 + g    ][kk + q4 + 4]);
                a[i][3] = __float_as_uint(As[s][wm + i * 16 + g + 8][kk + q4 + 4]);
            }
#pragma unroll
            for (int j = 0; j < 6; j++) {
                bf[j][0] = __float_as_uint(Bs[s][wn + j * 8 + g][kk + q4    ]);
                bf[j][1] = __float_as_uint(Bs[s][wn + j * 8 + g][kk + q4 + 4]);
            }
#pragma unroll
            for (int i = 0; i < 2; i++)
#pragma unroll
                for (int j = 0; j < 6; j++) mma8(acc[i][j], a[i], bf[j]);
        }
    }

    float* S = g_scores + (size_t)b * O_ * CP_;
#pragma unroll
    for (int i = 0; i < 2; i++)
#pragma unroll
        for (int j = 0; j < 6; j++) {
            int m = m0 + wm + i * 16 + g;
            int n = n0 + wn + j * 8 + 2 * q4;
            if (n < CP_) {
                if (m < O_)
                    *(float2*)(S + (size_t)m * CP_ + n) = make_float2(acc[i][j][0], acc[i][j][1]);
                if (m + 8 < O_)
                    *(float2*)(S + (size_t)(m + 8) * CP_ + n) = make_float2(acc[i][j][2], acc[i][j][3]);
            }
        }
}

// ---------------------------------------------------------------------------
// Kernel 3: softmax over channels (273 real), stride 288, pads -> 0, tf32 out
// ---------------------------------------------------------------------------
__global__ __launch_bounds__(256) void softmax_kernel() {
    int warp = (blockIdx.x * blockDim.x + threadIdx.x) >> 5;
    int lane = threadIdx.x & 31;
    if (warp >= B_ * O_) return;
    float* row = g_scores + (size_t)warp * CP_;

    float v[9];
    float m = -INFINITY;
#pragma unroll
    for (int i = 0; i < 9; i++) {
        int c = lane + i * 32;
        v[i] = (c < C_) ? row[c] : -INFINITY;
        m = fmaxf(m, v[i]);
    }
#pragma unroll
    for (int o = 16; o; o >>= 1) m = fmaxf(m, __shfl_xor_sync(0xffffffffu, m, o));
    float s = 0.f;
#pragma unroll
    for (int i = 0; i < 9; i++) {
        int c = lane + i * 32;
        if (c < C_) { v[i] = expf(v[i] - m); s += v[i]; }
    }
#pragma unroll
    for (int o = 16; o; o >>= 1) s += __shfl_xor_sync(0xffffffffu, s, o);
    float inv = 1.f / s;
#pragma unroll
    for (int i = 0; i < 9; i++) {
        int c = lane + i * 32;
        row[c] = (c < C_) ? tf32f(v[i] * inv) : 0.f;
    }
}

// ---------------------------------------------------------------------------
// Kernel 4: out[b,o,t] = sum_c W[b,o,c] * brain[b,c,t]
// mma.sync tf32, CTA 64x128, 4 warps (1x4, warp-tile 64x32), K-chunk 32,
// double buffer, ONE syncthreads per k-block. 16 mma / 24 aux per k8.
// ---------------------------------------------------------------------------
__global__ __launch_bounds__(128) void out_kernel(const float* __restrict__ brain,
                                                  float* __restrict__ out) {
    __shared__ float As[2][64][36];    // [m][k32], stride 36 -> bank 4g+q4, clean
    __shared__ float Bs[2][32][136];   // [k32][n], stride 136 -> bank 8q4+g, clean
    int b  = blockIdx.z;
    int m0 = blockIdx.y * 64;
    int n0 = blockIdx.x * 128;
    const float* W = g_scores + (size_t)b * O_ * CP_;
    const float* X = brain    + (size_t)b * C_ * T_;
    int t = threadIdx.x;
    int w = t >> 5, lane = t & 31;
    int wn = w * 32;                 // warp tile 64(m) x 32(n)
    int g = lane >> 2, q4 = lane & 3;

    float acc[4][4][4] = {};         // [mi][nj][4]

    auto load = [&](int kb, int s) {
        int k0 = kb * 32;
        {   // A: 64 x 32 floats = 512 float4, 4 per thread
#pragma unroll
            for (int q = 0; q < 4; q++) {
                int idx = t + 128 * q;
                int r = idx >> 3, c4 = (idx & 7) * 4;
                bool pa = (m0 + r) < O_;
                cp16(&As[s][r][c4], W + (size_t)(pa ? m0 + r : 0) * CP_ + k0 + c4, pa);
            }
        }
#pragma unroll
        for (int q = 0; q < 8; q++) {   // B: 32 x 128 floats = 1024 float4, 8 per thread
            int idx = t + 128 * q;
            int r = idx >> 5, c4 = (idx & 31) * 4;
            int kk = k0 + r, n = n0 + c4;
            bool pb = (kk < C_) && (n < T_);
            cp16(&Bs[s][r][c4], X + (size_t)(pb ? kk : 0) * T_ + (pb ? n : 0), pb);
        }
        CP_COMMIT();
    };

    load(0, 0);
    const int KB = CP_ / 32;   // 9
    for (int kb = 0; kb < KB; kb++) {
        int s = kb & 1;
        CP_WAIT0();
        __syncthreads();
        if (kb + 1 < KB) load(kb + 1, s ^ 1);
#pragma unroll
        for (int k8 = 0; k8 < 4; k8++) {
            int kk = k8 * 8;
            unsigned a[4][4], bf[4][2];
#pragma unroll
            for (int i = 0; i < 4; i++) {   // weights pre-rounded: no cvt
                a[i][0] = __float_as_uint(As[s][i * 16 + g    ][kk + q4    ]);
                a[i][1] = __float_as_uint(As[s][i * 16 + g + 8][kk + q4    ]);
                a[i][2] = __float_as_uint(As[s][i * 16 + g    ][kk + q4 + 4]);
                a[i][3] = __float_as_uint(As[s][i * 16 + g + 8][kk + q4 + 4]);
            }
#pragma unroll
            for (int j = 0; j < 4; j++) {
                bf[j][0] = tf32b(Bs[s][kk + q4    ][wn + j * 8 + g]);
                bf[j][1] = tf32b(Bs[s][kk + q4 + 4][wn + j * 8 + g]);
            }
#pragma unroll
            for (int i = 0; i < 4; i++)
#pragma unroll
                for (int j = 0; j < 4; j++) mma8(acc[i][j], a[i], bf[j]);
        }
    }

    float* Ob = out + (size_t)b * O_ * T_;
#pragma unroll
    for (int i = 0; i < 4; i++)
#pragma unroll
        for (int j = 0; j < 4; j++) {
            int m = m0 + i * 16 + g;
            int n = n0 + wn + j * 8 + 2 * q4;
            if (n < T_) {
                if (m < O_)
                    *(float2*)(Ob + (size_t)m * T_ + n) = make_float2(acc[i][j][0], acc[i][j][1]);
                if (m + 8 < O_)
                    *(float2*)(Ob + (size_t)(m + 8) * T_ + n) = make_float2(acc[i][j][2], acc[i][j][3]);
            }
        }
}

// ---------------------------------------------------------------------------
extern "C" void kernel_launch(void* const* d_in, const int* in_sizes, int n_in,
                              void* d_out, int out_size) {
    const float* brain  = (const float*)d_in[0];  // [32, 273, 3000]
    const float* layout = (const float*)d_in[1];  // [32, 273, 2]
    const float* heads  = (const float*)d_in[2];  // [270, 2048]
    float* out = (float*)d_out;                   // [32, 270, 3000]

    round_heads_kernel<<<(O_ * D_ + 255) / 256, 256>>>(heads);
    emb_kernel<<<B_ * C_, 256>>>(layout);
    scores_kernel<<<dim3(3, 3, B_), 192>>>();               // 96x96 tiles
    softmax_kernel<<<(B_ * O_ * 32 + 255) / 256, 256>>>();
    out_kernel<<<dim3(24, 5, B_), 128>>>(brain, out);       // 128n x 64m tiles
}

// round 6
// speedup vs baseline: 8.7558x; 1.2740x over previous
#include <cuda_runtime.h>
#include <cuda_fp16.h>
#include <math.h>

// Problem constants
#define B_  32
#define C_  273
#define CP_ 288    // padded channel dim
#define T_  3000
#define O_  270
#define D_  2048   // 2 * 32^2

// Scratch (allocation-free rule: __device__ globals)
__device__ __half g_emb[(size_t)B_ * C_ * D_];      // [B*C, 2048] fp16
__device__ float  g_scores[(size_t)B_ * O_ * CP_];  // raw scores fp32
__device__ __half g_wh[(size_t)B_ * O_ * CP_];      // softmax weights fp16, pads=0
__device__ __half g_headsh[(size_t)O_ * D_];        // heads fp16

// ---------------------------------------------------------------------------
// helpers
// ---------------------------------------------------------------------------
__device__ __forceinline__ void cp16(void* dst, const void* src, bool p) {
    unsigned d = (unsigned)__cvta_generic_to_shared(dst);
    int sz = p ? 16 : 0;
    asm volatile("cp.async.ca.shared.global [%0], [%1], 16, %2;" :: "r"(d), "l"(src), "r"(sz));
}
#define CP_COMMIT() asm volatile("cp.async.commit_group;")
#define CP_WAIT0()  asm volatile("cp.async.wait_group 0;")

__device__ __forceinline__ void mma16(float* c, const unsigned* a, const unsigned* b) {
    asm volatile("mma.sync.aligned.m16n8k16.row.col.f32.f16.f16.f32 "
        "{%0,%1,%2,%3},{%4,%5,%6,%7},{%8,%9},{%0,%1,%2,%3};"
        : "+f"(c[0]), "+f"(c[1]), "+f"(c[2]), "+f"(c[3])
        : "r"(a[0]), "r"(a[1]), "r"(a[2]), "r"(a[3]), "r"(b[0]), "r"(b[1]));
}

// packs {lo, hi} into one f16x2 register with a single cvt
__device__ __forceinline__ unsigned pack_h2(float lo, float hi) {
    unsigned d; asm("cvt.rn.f16x2.f32 %0, %1, %2;" : "=r"(d) : "f"(hi), "f"(lo)); return d;
}

// ---------------------------------------------------------------------------
// Kernel 0: heads -> fp16
// ---------------------------------------------------------------------------
__global__ __launch_bounds__(256) void heads_kernel(const float* __restrict__ heads) {
    int i = blockIdx.x * 256 + threadIdx.x;
    if (i < O_ * D_) g_headsh[i] = __float2half(heads[i]);
}

// ---------------------------------------------------------------------------
// Kernel 1: fourier embedding (angle addition), fp16 output
// ---------------------------------------------------------------------------
__global__ __launch_bounds__(256) void emb_kernel(const float* __restrict__ layout) {
    __shared__ float sx[32], cx[32], sy[32], cy[32];
    int bc = blockIdx.x;
    float px = (layout[bc * 2 + 0] + 0.1f) / 1.2f;
    float py = (layout[bc * 2 + 1] + 0.1f) / 1.2f;
    if (threadIdx.x < 64) {
        int axis = threadIdx.x >> 5;
        int i = threadIdx.x & 31;
        float p = axis ? py : px;
        float t = p * (float)i;
        t -= floorf(t);
        float s, c;
        sincosf(6.28318530717958647692f * t, &s, &c);
        if (axis == 0) { sx[i] = s; cx[i] = c; }
        else           { sy[i] = s; cy[i] = c; }
    }
    __syncthreads();
    __half* e = g_emb + (size_t)bc * D_;
    for (int idx = threadIdx.x; idx < 1024; idx += 256) {
        int i = idx >> 5, j = idx & 31;
        float si = sx[i], ci = cx[i], sj = sy[j], cj = cy[j];
        e[idx]        = __float2half(si * cj + ci * sj);   // sin(a+b)
        e[idx + 1024] = __float2half(ci * cj - si * sj);   // cos(a+b)
    }
}

// ---------------------------------------------------------------------------
// Kernel 2: scores[b,o,c] = sum_d headsh[o,d] * emb[b,c,d]  (both fp16 k-major)
// mma.sync m16n8k16 f16, CTA 96x96, 6 warps (3x2, warp 32x48), K-chunk 32.
// ---------------------------------------------------------------------------
__global__ __launch_bounds__(192) void scores_kernel() {
    __shared__ __half As[2][96][40];   // stride 40 halves -> banks 20g+q4, clean
    __shared__ __half Bs[2][96][40];
    int b  = blockIdx.z;
    int m0 = blockIdx.y * 96;
    int n0 = blockIdx.x * 96;
    const __half* E = g_emb + (size_t)b * C_ * D_;
    int t = threadIdx.x;
    int w = t >> 5, lane = t & 31;
    int wm = (w >> 1) * 32, wn = (w & 1) * 48;
    int g = lane >> 2, q4 = lane & 3;

    float acc[2][6][4] = {};

    auto load = [&](int kb, int s) {
        int k0 = kb * 32;
#pragma unroll
        for (int q = 0; q < 2; q++) {
            int idx = t + 192 * q;
            int r = idx >> 2, c8 = (idx & 3) * 8;
            bool pa = (m0 + r) < O_;
            cp16(&As[s][r][c8], g_headsh + (size_t)(pa ? m0 + r : 0) * D_ + k0 + c8, pa);
            bool pb = (n0 + r) < C_;
            cp16(&Bs[s][r][c8], E + (size_t)(pb ? n0 + r : 0) * D_ + k0 + c8, pb);
        }
        CP_COMMIT();
    };

    load(0, 0);
    const int KB = D_ / 32;   // 64
    for (int kb = 0; kb < KB; kb++) {
        int s = kb & 1;
        CP_WAIT0();
        __syncthreads();
        if (kb + 1 < KB) load(kb + 1, s ^ 1);
#pragma unroll
        for (int k16 = 0; k16 < 2; k16++) {
            int kk = k16 * 16;
            unsigned a[2][4], bf[6][2];
#pragma unroll
            for (int i = 0; i < 2; i++) {
                a[i][0] = *(const unsigned*)&As[s][wm + i * 16 + g    ][kk + 2 * q4];
                a[i][1] = *(const unsigned*)&As[s][wm + i * 16 + g + 8][kk + 2 * q4];
                a[i][2] = *(const unsigned*)&As[s][wm + i * 16 + g    ][kk + 2 * q4 + 8];
                a[i][3] = *(const unsigned*)&As[s][wm + i * 16 + g + 8][kk + 2 * q4 + 8];
            }
#pragma unroll
            for (int j = 0; j < 6; j++) {
                bf[j][0] = *(const unsigned*)&Bs[s][wn + j * 8 + g][kk + 2 * q4];
                bf[j][1] = *(const unsigned*)&Bs[s][wn + j * 8 + g][kk + 2 * q4 + 8];
            }
#pragma unroll
            for (int i = 0; i < 2; i++)
#pragma unroll
                for (int j = 0; j < 6; j++) mma16(acc[i][j], a[i], bf[j]);
        }
    }

    float* S = g_scores + (size_t)b * O_ * CP_;
#pragma unroll
    for (int i = 0; i < 2; i++)
#pragma unroll
        for (int j = 0; j < 6; j++) {
            int m = m0 + wm + i * 16 + g;
            int n = n0 + wn + j * 8 + 2 * q4;
            if (n < CP_) {
                if (m < O_)
                    *(float2*)(S + (size_t)m * CP_ + n) = make_float2(acc[i][j][0], acc[i][j][1]);
                if (m + 8 < O_)
                    *(float2*)(S + (size_t)(m + 8) * CP_ + n) = make_float2(acc[i][j][2], acc[i][j][3]);
            }
        }
}

// ---------------------------------------------------------------------------
// Kernel 3: softmax over channels (273 real), writes fp16 weights, pads -> 0
// ---------------------------------------------------------------------------
__global__ __launch_bounds__(256) void softmax_kernel() {
    int warp = (blockIdx.x * blockDim.x + threadIdx.x) >> 5;
    int lane = threadIdx.x & 31;
    if (warp >= B_ * O_) return;
    const float* row = g_scores + (size_t)warp * CP_;
    __half* roww = g_wh + (size_t)warp * CP_;

    float v[9];
    float m = -INFINITY;
#pragma unroll
    for (int i = 0; i < 9; i++) {
        int c = lane + i * 32;
        v[i] = (c < C_) ? row[c] : -INFINITY;
        m = fmaxf(m, v[i]);
    }
#pragma unroll
    for (int o = 16; o; o >>= 1) m = fmaxf(m, __shfl_xor_sync(0xffffffffu, m, o));
    float s = 0.f;
#pragma unroll
    for (int i = 0; i < 9; i++) {
        int c = lane + i * 32;
        if (c < C_) { v[i] = expf(v[i] - m); s += v[i]; }
    }
#pragma unroll
    for (int o = 16; o; o >>= 1) s += __shfl_xor_sync(0xffffffffu, s, o);
    float inv = 1.f / s;
#pragma unroll
    for (int i = 0; i < 9; i++) {
        int c = lane + i * 32;
        roww[c] = (c < C_) ? __float2half(v[i] * inv) : __float2half(0.f);
    }
}

// ---------------------------------------------------------------------------
// Kernel 4: out[b,o,t] = sum_c W[b,o,c] * brain[b,c,t]
// A = fp16 weights (k-major), B = fp32 brain packed to f16x2 in-register.
// mma.sync m16n8k16, CTA 64x128, 4 warps (warp-tile 64x32), K-chunk 32.
// ---------------------------------------------------------------------------
__global__ __launch_bounds__(128) void out_kernel(const float* __restrict__ brain,
                                                  float* __restrict__ out) {
    __shared__ __half As[2][64][40];    // stride 40h -> banks 20g+q4, clean
    __shared__ float  Bs[2][32][132];   // stride 132 -> row 2q4 banks 8q4+g, clean
    int b  = blockIdx.z;
    int m0 = blockIdx.y * 64;
    int n0 = blockIdx.x * 128;
    const __half* W = g_wh + (size_t)b * O_ * CP_;
    const float*  X = brain + (size_t)b * C_ * T_;
    int t = threadIdx.x;
    int w = t >> 5, lane = t & 31;
    int wn = w * 32;                 // warp tile 64(m) x 32(n)
    int g = lane >> 2, q4 = lane & 3;

    float acc[4][4][4] = {};         // [mi][nj][4]

    auto load = [&](int kb, int s) {
        int k0 = kb * 32;
#pragma unroll
        for (int q = 0; q < 2; q++) {   // A: 64 rows x 32 halves = 256 cp16
            int idx = t + 128 * q;
            int r = idx >> 2, c8 = (idx & 3) * 8;
            bool pa = (m0 + r) < O_;
            cp16(&As[s][r][c8], W + (size_t)(pa ? m0 + r : 0) * CP_ + k0 + c8, pa);
        }
#pragma unroll
        for (int q = 0; q < 8; q++) {   // B: 32 x 128 floats = 1024 cp16
            int idx = t + 128 * q;
            int r = idx >> 5, c4 = (idx & 31) * 4;
            int kk = k0 + r, n = n0 + c4;
            bool pb = (kk < C_) && (n < T_);
            cp16(&Bs[s][r][c4], X + (size_t)(pb ? kk : 0) * T_ + (pb ? n : 0), pb);
        }
        CP_COMMIT();
    };

    load(0, 0);
    const int KB = CP_ / 32;   // 9
    for (int kb = 0; kb < KB; kb++) {
        int s = kb & 1;
        CP_WAIT0();
        __syncthreads();
        if (kb + 1 < KB) load(kb + 1, s ^ 1);
#pragma unroll
        for (int k16 = 0; k16 < 2; k16++) {
            int kk = k16 * 16;
            unsigned a[4][4], bf[4][2];
#pragma unroll
            for (int i = 0; i < 4; i++) {
                a[i][0] = *(const unsigned*)&As[s][i * 16 + g    ][kk + 2 * q4];
                a[i][1] = *(const unsigned*)&As[s][i * 16 + g + 8][kk + 2 * q4];
                a[i][2] = *(const unsigned*)&As[s][i * 16 + g    ][kk + 2 * q4 + 8];
                a[i][3] = *(const unsigned*)&As[s][i * 16 + g + 8][kk + 2 * q4 + 8];
            }
#pragma unroll
            for (int j = 0; j < 4; j++) {
                int n = wn + j * 8 + g;
                bf[j][0] = pack_h2(Bs[s][kk + 2 * q4    ][n], Bs[s][kk + 2 * q4 + 1][n]);
                bf[j][1] = pack_h2(Bs[s][kk + 2 * q4 + 8][n], Bs[s][kk + 2 * q4 + 9][n]);
            }
#pragma unroll
            for (int i = 0; i < 4; i++)
#pragma unroll
                for (int j = 0; j < 4; j++) mma16(acc[i][j], a[i], bf[j]);
        }
    }

    float* Ob = out + (size_t)b * O_ * T_;
#pragma unroll
    for (int i = 0; i < 4; i++)
#pragma unroll
        for (int j = 0; j < 4; j++) {
            int m = m0 + i * 16 + g;
            int n = n0 + wn + j * 8 + 2 * q4;
            if (n < T_) {
                if (m < O_)
                    *(float2*)(Ob + (size_t)m * T_ + n) = make_float2(acc[i][j][0], acc[i][j][1]);
                if (m + 8 < O_)
                    *(float2*)(Ob + (size_t)(m + 8) * T_ + n) = make_float2(acc[i][j][2], acc[i][j][3]);
            }
        }
}

// ---------------------------------------------------------------------------
extern "C" void kernel_launch(void* const* d_in, const int* in_sizes, int n_in,
                              void* d_out, int out_size) {
    const float* brain  = (const float*)d_in[0];  // [32, 273, 3000]
    const float* layout = (const float*)d_in[1];  // [32, 273, 2]
    const float* heads  = (const float*)d_in[2];  // [270, 2048]
    float* out = (float*)d_out;                   // [32, 270, 3000]

    heads_kernel<<<(O_ * D_ + 255) / 256, 256>>>(heads);
    emb_kernel<<<B_ * C_, 256>>>(layout);
    scores_kernel<<<dim3(3, 3, B_), 192>>>();               // 96x96 tiles
    softmax_kernel<<<(B_ * O_ * 32 + 255) / 256, 256>>>();
    out_kernel<<<dim3(24, 5, B_), 128>>>(brain, out);       // 128n x 64m tiles
}

// round 7
// speedup vs baseline: 10.5508x; 1.2050x over previous
#include <cuda_runtime.h>
#include <cuda_fp16.h>
#include <math.h>

// Problem constants
#define B_  32
#define C_  273
#define CP_ 288    // padded channel dim
#define T_  3000
#define O_  270
#define D_  2048   // 2 * 32^2

// Scratch (allocation-free rule: __device__ globals)
__device__ __half g_emb[(size_t)B_ * C_ * D_];      // [B*C, 2048] fp16
__device__ float  g_scores[(size_t)B_ * O_ * CP_];  // raw scores fp32
__device__ __half g_wh[(size_t)B_ * O_ * CP_];      // softmax weights fp16, pads=0
__device__ __half g_headsh[(size_t)O_ * D_];        // heads fp16
__device__ __half g_brainh[(size_t)B_ * C_ * T_];   // brain fp16

// ---------------------------------------------------------------------------
// helpers
// ---------------------------------------------------------------------------
__device__ __forceinline__ void cp16(void* dst, const void* src, bool p) {
    unsigned d = (unsigned)__cvta_generic_to_shared(dst);
    int sz = p ? 16 : 0;
    asm volatile("cp.async.ca.shared.global [%0], [%1], 16, %2;" :: "r"(d), "l"(src), "r"(sz));
}
#define CP_COMMIT() asm volatile("cp.async.commit_group;")
#define CP_WAIT0()  asm volatile("cp.async.wait_group 0;")

__device__ __forceinline__ void mma16(float* c, const unsigned* a, const unsigned* b) {
    asm volatile("mma.sync.aligned.m16n8k16.row.col.f32.f16.f16.f32 "
        "{%0,%1,%2,%3},{%4,%5,%6,%7},{%8,%9},{%0,%1,%2,%3};"
        : "+f"(c[0]), "+f"(c[1]), "+f"(c[2]), "+f"(c[3])
        : "r"(a[0]), "r"(a[1]), "r"(a[2]), "r"(a[3]), "r"(b[0]), "r"(b[1]));
}

__device__ __forceinline__ void ldsm4(unsigned* r, const void* p) {
    unsigned a = (unsigned)__cvta_generic_to_shared(p);
    asm volatile("ldmatrix.sync.aligned.m8n8.x4.shared.b16 {%0,%1,%2,%3}, [%4];"
        : "=r"(r[0]), "=r"(r[1]), "=r"(r[2]), "=r"(r[3]) : "r"(a));
}
__device__ __forceinline__ void ldsm2(unsigned* r, const void* p) {
    unsigned a = (unsigned)__cvta_generic_to_shared(p);
    asm volatile("ldmatrix.sync.aligned.m8n8.x2.shared.b16 {%0,%1}, [%2];"
        : "=r"(r[0]), "=r"(r[1]) : "r"(a));
}
__device__ __forceinline__ void ldsm2t(unsigned* r, const void* p) {
    unsigned a = (unsigned)__cvta_generic_to_shared(p);
    asm volatile("ldmatrix.sync.aligned.m8n8.x2.trans.shared.b16 {%0,%1}, [%2];"
        : "=r"(r[0]), "=r"(r[1]) : "r"(a));
}

// ---------------------------------------------------------------------------
// Kernel 0a: heads -> fp16
// ---------------------------------------------------------------------------
__global__ __launch_bounds__(256) void heads_kernel(const float* __restrict__ heads) {
    int i = blockIdx.x * 256 + threadIdx.x;
    if (i < O_ * D_) g_headsh[i] = __float2half(heads[i]);
}

// ---------------------------------------------------------------------------
// Kernel 0b: brain -> fp16 (streaming, 8 elems/thread; 26208000 % 8 == 0)
// ---------------------------------------------------------------------------
__global__ __launch_bounds__(256) void brain_kernel(const float* __restrict__ brain) {
    size_t i = ((size_t)blockIdx.x * 256 + threadIdx.x) * 8;
    if (i >= (size_t)B_ * C_ * T_) return;
    float4 a = *(const float4*)(brain + i);
    float4 b = *(const float4*)(brain + i + 4);
    __half2 h[4];
    h[0] = __floats2half2_rn(a.x, a.y);
    h[1] = __floats2half2_rn(a.z, a.w);
    h[2] = __floats2half2_rn(b.x, b.y);
    h[3] = __floats2half2_rn(b.z, b.w);
    *(uint4*)(g_brainh + i) = *(uint4*)h;
}

// ---------------------------------------------------------------------------
// Kernel 1: fourier embedding (angle addition), fp16 half2 output
// ---------------------------------------------------------------------------
__global__ __launch_bounds__(256) void emb_kernel(const float* __restrict__ layout) {
    __shared__ float sx[32], cx[32], sy[32], cy[32];
    int bc = blockIdx.x;
    float px = (layout[bc * 2 + 0] + 0.1f) / 1.2f;
    float py = (layout[bc * 2 + 1] + 0.1f) / 1.2f;
    if (threadIdx.x < 64) {
        int axis = threadIdx.x >> 5;
        int i = threadIdx.x & 31;
        float p = axis ? py : px;
        float t = p * (float)i;
        t -= floorf(t);
        float s, c;
        sincosf(6.28318530717958647692f * t, &s, &c);
        if (axis == 0) { sx[i] = s; cx[i] = c; }
        else           { sy[i] = s; cy[i] = c; }
    }
    __syncthreads();
    __half2* e = (__half2*)(g_emb + (size_t)bc * D_);
    for (int p2 = threadIdx.x; p2 < 512; p2 += 256) {
        int i = p2 >> 4, j = (p2 & 15) * 2;
        float si = sx[i], ci = cx[i];
        float s0 = sy[j], c0 = cy[j], s1 = sy[j + 1], c1 = cy[j + 1];
        e[p2]       = __floats2half2_rn(si * c0 + ci * s0, si * c1 + ci * s1);  // sin
        e[p2 + 512] = __floats2half2_rn(ci * c0 - si * s0, ci * c1 - si * s1);  // cos
    }
}

// ---------------------------------------------------------------------------
// Kernel 2: scores[b,o,c] = sum_d headsh[o,d] * emb[b,c,d]  (both fp16 k-major)
// mma.sync m16n8k16, CTA 96x96, 6 warps (3x2, warp 32x48), K-chunk 32,
// ldmatrix for all fragments.
// ---------------------------------------------------------------------------
__global__ __launch_bounds__(192) void scores_kernel() {
    __shared__ __half As[2][96][40];   // stride 40h: LDSM rows step 20 banks, clean
    __shared__ __half Bs[2][96][40];
    int b  = blockIdx.z;
    int m0 = blockIdx.y * 96;
    int n0 = blockIdx.x * 96;
    const __half* E = g_emb + (size_t)b * C_ * D_;
    int t = threadIdx.x;
    int w = t >> 5, lane = t & 31;
    int wm = (w >> 1) * 32, wn = (w & 1) * 48;
    int g = lane >> 2, q4 = lane & 3;
    int l15 = lane & 15, lhi = (lane >> 4) << 3;   // A ldsm addressing
    int l7 = lane & 7,  lk8 = ((lane >> 3) & 1) << 3;  // B ldsm addressing

    float acc[2][6][4] = {};

    auto load = [&](int kb, int s) {
        int k0 = kb * 32;
#pragma unroll
        for (int q = 0; q < 2; q++) {
            int idx = t + 192 * q;
            int r = idx >> 2, c8 = (idx & 3) * 8;
            bool pa = (m0 + r) < O_;
            cp16(&As[s][r][c8], g_headsh + (size_t)(pa ? m0 + r : 0) * D_ + k0 + c8, pa);
            bool pb = (n0 + r) < C_;
            cp16(&Bs[s][r][c8], E + (size_t)(pb ? n0 + r : 0) * D_ + k0 + c8, pb);
        }
        CP_COMMIT();
    };

    load(0, 0);
    const int KB = D_ / 32;   // 64
    for (int kb = 0; kb < KB; kb++) {
        int s = kb & 1;
        CP_WAIT0();
        __syncthreads();
        if (kb + 1 < KB) load(kb + 1, s ^ 1);
#pragma unroll
        for (int k16 = 0; k16 < 2; k16++) {
            int kk = k16 * 16;
            unsigned a[2][4], bf[6][2];
#pragma unroll
            for (int i = 0; i < 2; i++)
                ldsm4(a[i], &As[s][wm + i * 16 + l15][kk + lhi]);
#pragma unroll
            for (int j = 0; j < 6; j++)
                ldsm2(bf[j], &Bs[s][wn + j * 8 + l7][kk + lk8]);
#pragma unroll
            for (int i = 0; i < 2; i++)
#pragma unroll
                for (int j = 0; j < 6; j++) mma16(acc[i][j], a[i], bf[j]);
        }
    }

    float* S = g_scores + (size_t)b * O_ * CP_;
#pragma unroll
    for (int i = 0; i < 2; i++)
#pragma unroll
        for (int j = 0; j < 6; j++) {
            int m = m0 + wm + i * 16 + g;
            int n = n0 + wn + j * 8 + 2 * q4;
            if (n < CP_) {
                if (m < O_)
                    *(float2*)(S + (size_t)m * CP_ + n) = make_float2(acc[i][j][0], acc[i][j][1]);
                if (m + 8 < O_)
                    *(float2*)(S + (size_t)(m + 8) * CP_ + n) = make_float2(acc[i][j][2], acc[i][j][3]);
            }
        }
}

// ---------------------------------------------------------------------------
// Kernel 3: softmax over channels (273 real), writes fp16 weights, pads -> 0
// ---------------------------------------------------------------------------
__global__ __launch_bounds__(256) void softmax_kernel() {
    int warp = (blockIdx.x * blockDim.x + threadIdx.x) >> 5;
    int lane = threadIdx.x & 31;
    if (warp >= B_ * O_) return;
    const float* row = g_scores + (size_t)warp * CP_;
    __half* roww = g_wh + (size_t)warp * CP_;

    float v[9];
    float m = -INFINITY;
#pragma unroll
    for (int i = 0; i < 9; i++) {
        int c = lane + i * 32;
        v[i] = (c < C_) ? row[c] : -INFINITY;
        m = fmaxf(m, v[i]);
    }
#pragma unroll
    for (int o = 16; o; o >>= 1) m = fmaxf(m, __shfl_xor_sync(0xffffffffu, m, o));
    float s = 0.f;
#pragma unroll
    for (int i = 0; i < 9; i++) {
        int c = lane + i * 32;
        if (c < C_) { v[i] = expf(v[i] - m); s += v[i]; }
    }
#pragma unroll
    for (int o = 16; o; o >>= 1) s += __shfl_xor_sync(0xffffffffu, s, o);
    float inv = 1.f / s;
#pragma unroll
    for (int i = 0; i < 9; i++) {
        int c = lane + i * 32;
        roww[c] = (c < C_) ? __float2half(v[i] * inv) : __float2half(0.f);
    }
}

// ---------------------------------------------------------------------------
// Kernel 4: out[b,o,t] = sum_c W[b,o,c] * brainh[b,c,t]  (all fp16 operands)
// mma.sync m16n8k16, CTA 64x128, 4 warps (warp-tile 64x32), K-chunk 32.
// A via ldmatrix.x4, B via ldmatrix.x2.trans (brain rows are k-major).
// ---------------------------------------------------------------------------
__global__ __launch_bounds__(128) void out_kernel(float* __restrict__ out) {
    __shared__ __half As[2][64][40];    // stride 40h
    __shared__ __half Bs[2][32][136];   // stride 136h: trans-LDSM rows step 4 banks, clean
    int b  = blockIdx.z;
    int m0 = blockIdx.y * 64;
    int n0 = blockIdx.x * 128;
    const __half* W = g_wh + (size_t)b * O_ * CP_;
    const __half* X = g_brainh + (size_t)b * C_ * T_;
    int t = threadIdx.x;
    int w = t >> 5, lane = t & 31;
    int wn = w * 32;                 // warp tile 64(m) x 32(n)
    int g = lane >> 2, q4 = lane & 3;
    int l15 = lane & 15, lhi = (lane >> 4) << 3;
    int bkrow = (lane & 7) + (((lane >> 3) & 1) << 3);   // trans-B k row

    float acc[4][4][4] = {};         // [mi][nj][4]

    auto load = [&](int kb, int s) {
        int k0 = kb * 32;
#pragma unroll
        for (int q = 0; q < 2; q++) {   // A: 64 rows x 32 halves = 256 cp16
            int idx = t + 128 * q;
            int r = idx >> 2, c8 = (idx & 3) * 8;
            bool pa = (m0 + r) < O_;
            cp16(&As[s][r][c8], W + (size_t)(pa ? m0 + r : 0) * CP_ + k0 + c8, pa);
        }
#pragma unroll
        for (int q = 0; q < 4; q++) {   // B: 32 rows x 128 halves = 512 cp16
            int idx = t + 128 * q;
            int r = idx >> 4, c8 = (idx & 15) * 8;
            int kk = k0 + r, n = n0 + c8;
            bool pb = (kk < C_) && (n < T_);   // chunks are 8-aligned; T%8==0, no straddle
            cp16(&Bs[s][r][c8], X + (size_t)(pb ? kk : 0) * T_ + (pb ? n : 0), pb);
        }
        CP_COMMIT();
    };

    load(0, 0);
    const int KB = CP_ / 32;   // 9
    for (int kb = 0; kb < KB; kb++) {
        int s = kb & 1;
        CP_WAIT0();
        __syncthreads();
        if (kb + 1 < KB) load(kb + 1, s ^ 1);
#pragma unroll
        for (int k16 = 0; k16 < 2; k16++) {
            int kk = k16 * 16;
            unsigned a[4][4], bf[4][2];
#pragma unroll
            for (int i = 0; i < 4; i++)
                ldsm4(a[i], &As[s][i * 16 + l15][kk + lhi]);
#pragma unroll
            for (int j = 0; j < 4; j++)
                ldsm2t(bf[j], &Bs[s][kk + bkrow][wn + j * 8]);
#pragma unroll
            for (int i = 0; i < 4; i++)
#pragma unroll
                for (int j = 0; j < 4; j++) mma16(acc[i][j], a[i], bf[j]);
        }
    }

    float* Ob = out + (size_t)b * O_ * T_;
#pragma unroll
    for (int i = 0; i < 4; i++)
#pragma unroll
        for (int j = 0; j < 4; j++) {
            int m = m0 + i * 16 + g;
            int n = n0 + wn + j * 8 + 2 * q4;
            if (n < T_) {
                if (m < O_)
                    *(float2*)(Ob + (size_t)m * T_ + n) = make_float2(acc[i][j][0], acc[i][j][1]);
                if (m + 8 < O_)
                    *(float2*)(Ob + (size_t)(m + 8) * T_ + n) = make_float2(acc[i][j][2], acc[i][j][3]);
            }
        }
}

// ---------------------------------------------------------------------------
extern "C" void kernel_launch(void* const* d_in, const int* in_sizes, int n_in,
                              void* d_out, int out_size) {
    const float* brain  = (const float*)d_in[0];  // [32, 273, 3000]
    const float* layout = (const float*)d_in[1];  // [32, 273, 2]
    const float* heads  = (const float*)d_in[2];  // [270, 2048]
    float* out = (float*)d_out;                   // [32, 270, 3000]

    heads_kernel<<<(O_ * D_ + 255) / 256, 256>>>(heads);
    brain_kernel<<<(B_ * C_ * T_ / 8 + 255) / 256, 256>>>(brain);
    emb_kernel<<<B_ * C_, 256>>>(layout);
    scores_kernel<<<dim3(3, 3, B_), 192>>>();               // 96x96 tiles
    softmax_kernel<<<(B_ * O_ * 32 + 255) / 256, 256>>>();
    out_kernel<<<dim3(24, 5, B_), 128>>>(out);              // 128n x 64m tiles
}